// round 16
// baseline (speedup 1.0000x reference)
#include <cuda_runtime.h>
#include <cuda_fp16.h>
#include <cstdint>
#include <cmath>

constexpr int Bb=4, Tt=4096, SD=256, Cc=1024, Aa=64, Ll=6, Hh=16, BSz=64;
constexpr int Mm=Bb*Tt, HD=Cc/Hh;
constexpr float ATT_SCALE=0.125f, LN_EPS=1e-5f;

// transposed fp16 weights, packed (element offsets)
constexpr size_t SE_OFF=0;
constexpr size_t QKV_OFF=SE_OFF+1024UL*256, QKV_SZ=3072UL*1024;
constexpr size_t AO_OFF =QKV_OFF+6*QKV_SZ,  AO_SZ =1024UL*1024;
constexpr size_t W1_OFF =AO_OFF +6*AO_SZ,   W1_SZ =4096UL*1024;
constexpr size_t W2_OFF =W1_OFF +6*W1_SZ,   W2_SZ =1024UL*4096;
constexpr size_t WTOT   =W2_OFF +6*W2_SZ;

__device__ float g_x  [(size_t)Mm*Cc];       // residual stream (fp32)
__device__ float g_qkv[(size_t)Mm*3*Cc];     // qkv fp32 / final-LN fp32 reuse
__device__ __half g_sh[(size_t)Mm*SD];       // states fp16
__device__ __half g_hh[(size_t)Mm*Cc];       // LN out fp16
__device__ __half g_ch[(size_t)Mm*Cc];       // attn ctx fp16
__device__ __half g_mh[(size_t)Mm*4*Cc];     // mlp hidden fp16
__device__ __half g_wh[WTOT];                // weights fp16 [N][K]

// ---------- base-target PTX helpers ----------
__device__ __forceinline__ uint32_t smem_u32(const void* p){
    uint32_t a; asm("{ .reg .u64 t; cvta.to.shared.u64 t, %1; cvt.u32.u64 %0, t; }":"=r"(a):"l"(p)); return a;
}
__device__ __forceinline__ void cpa16(uint32_t dst, const void* src){
    asm volatile("cp.async.cg.shared.global [%0], [%1], 16;"::"r"(dst),"l"(src));
}
#define CP_COMMIT() asm volatile("cp.async.commit_group;":::"memory")
__device__ __forceinline__ void ldsm4(uint32_t* r, uint32_t a){
    asm volatile("ldmatrix.sync.aligned.m8n8.x4.shared.b16 {%0,%1,%2,%3}, [%4];"
        : "=r"(r[0]),"=r"(r[1]),"=r"(r[2]),"=r"(r[3]) : "r"(a));
}
__device__ __forceinline__ void mma16816(float* d, const uint32_t* a, const uint32_t* b){
    asm volatile("mma.sync.aligned.m16n8k16.row.col.f32.f16.f16.f32 "
        "{%0,%1,%2,%3}, {%4,%5,%6,%7}, {%8,%9}, {%0,%1,%2,%3};"
        : "+f"(d[0]),"+f"(d[1]),"+f"(d[2]),"+f"(d[3])
        : "r"(a[0]),"r"(a[1]),"r"(a[2]),"r"(a[3]), "r"(b[0]),"r"(b[1]));
}
__device__ __forceinline__ float gelu_exact(float x){
    return 0.5f*x*(1.0f+erff(x*0.70710678118654752f));
}

// ========== fp16 GEMM: out = EPI(A[M,K] @ Bt[N,K]^T + bias) ==========
// CTA tile 128(M) x 256(N), 16 warps (2M x 8N), warp tile 64x32, K-step 32, 3-stage cp.async.
// 4 warps/SMSP for latency hiding (vs 2 in the 8-warp variant).
// smem row: 32 fp16 (64B) at 80B stride (conflict-free ldmatrix).
// CP_COMMIT unconditional each iteration (empty groups keep wait_group accounting sound).
// EPI: 0 = fp32 out; 1 = gelu -> fp16; 2 = +aux residual fp32; 3 = +pos-embed fp32
constexpr int AOFF=0, BOFF=10240, STAGE=30720, GSMEM=3*STAGE;  // 92160 B
constexpr int GTHREADS=512;

template<int EPI>
__global__ __launch_bounds__(GTHREADS)
void gemmh(const __half* __restrict__ Ah, const __half* __restrict__ Bt,
           const float* __restrict__ bias, const float* __restrict__ aux,
           float* __restrict__ outF, __half* __restrict__ oH, int Nv, int K)
{
    extern __shared__ char smem[];
    const uint32_t sb = smem_u32(smem);
    const int tid=threadIdx.x, lane=tid&31, wid=tid>>5;
    const int wm=wid>>3, wn=wid&7;                 // 2 x 8 warps -> 64x32 tiles
    const int m0=blockIdx.y*128, n0=blockIdx.x*256;
    const int nk=K>>5;

    auto issue=[&](int buf,int k0){
        uint32_t ab=sb+buf*STAGE;
        {                                           // A: 128 rows x 4 chunks = 512
            int r=tid>>2, q=tid&3;
            cpa16(ab+AOFF+r*80+q*16, Ah+(size_t)(m0+r)*K+k0+q*8);
        }
#pragma unroll
        for(int i=0;i<2;i++){                       // B: 256 rows x 4 chunks = 1024
            int c=tid+i*GTHREADS;
            int r=c>>2, q=c&3;
            cpa16(ab+BOFF+r*80+q*16, Bt+(size_t)(n0+r)*K+k0+q*8);
        }
    };

    float acc[4][4][4];
#pragma unroll
    for(int a=0;a<4;a++)
#pragma unroll
    for(int b=0;b<4;b++)
#pragma unroll
    for(int c=0;c<4;c++) acc[a][b][c]=0.f;

    issue(0,0); CP_COMMIT();
    issue(1,32); CP_COMMIT();

    int buf=0;
    for(int s=0;s<nk;s++){
        asm volatile("cp.async.wait_group 1;":::"memory");
        __syncthreads();
        uint32_t ab=sb+buf*STAGE, bbs=ab+BOFF;
#pragma unroll
        for(int p=0;p<2;p++){
            uint32_t bfr[2][4];
#pragma unroll
            for(int ng=0;ng<2;ng++){
                uint32_t nrow=wn*32+ng*16+((lane>>4)&1)*8+(lane&7);
                uint32_t kby =((lane>>3)&1)*16+p*32;
                ldsm4(bfr[ng], bbs+nrow*80+kby);
            }
            uint32_t afr[4][4];
#pragma unroll
            for(int mt=0;mt<4;mt++){
                uint32_t row=wm*64+mt*16+((lane>>3)&1)*8+(lane&7);
                uint32_t kby=((lane>>4)&1)*16+p*32;
                ldsm4(afr[mt], ab+row*80+kby);
            }
#pragma unroll
            for(int mt=0;mt<4;mt++)
#pragma unroll
            for(int nt=0;nt<4;nt++)
                mma16816(acc[mt][nt], afr[mt], &bfr[nt>>1][(nt&1)*2]);
        }
        if(s+2<nk) issue((buf+2)%3,(s+2)*32);
        CP_COMMIT();                                 // unconditional
        buf=(buf+1)%3;
    }

    // ---- epilogue ----
#pragma unroll
    for(int mt=0;mt<4;mt++)
#pragma unroll
    for(int nt=0;nt<4;nt++){
        int col=n0+wn*32+nt*8+2*(lane&3);
        int r0=m0+wm*64+mt*16+(lane>>2);
        float2 bv=*(const float2*)(bias+col);
#pragma unroll
        for(int hrow=0;hrow<2;hrow++){
            int r=r0+hrow*8;
            float v0=acc[mt][nt][hrow*2+0]+bv.x;
            float v1=acc[mt][nt][hrow*2+1]+bv.y;
            size_t o=(size_t)r*Nv+col;
            if(EPI==1){
                v0=gelu_exact(v0); v1=gelu_exact(v1);
                __half2 hp; hp.x=__float2half_rn(v0); hp.y=__float2half_rn(v1);
                *(__half2*)(oH+o)=hp;
            } else if(EPI==2){
                float2 ax=*(const float2*)(aux+o);
                *(float2*)(outF+o)=make_float2(v0+ax.x, v1+ax.y);
            } else if(EPI==3){
                float2 ax=*(const float2*)(aux+(size_t)(r&(Tt-1))*Nv+col);
                *(float2*)(outF+o)=make_float2(v0+ax.x, v1+ax.y);
            } else {
                *(float2*)(outF+o)=make_float2(v0,v1);
            }
        }
    }
}

// ---------- weight transpose + fp16: W[K,N] -> Wt[N,K] ----------
__global__ __launch_bounds__(256)
void trk(const float* __restrict__ W, __half* __restrict__ Wt, int K, int N)
{
    __shared__ float t[32][33];
    int n0=blockIdx.x*32, k0=blockIdx.y*32;
    int tx=threadIdx.x&31, ty=threadIdx.x>>5;
#pragma unroll
    for(int i=0;i<4;i++) t[ty+i*8][tx]=W[(size_t)(k0+ty+i*8)*N+n0+tx];
    __syncthreads();
#pragma unroll
    for(int i=0;i<4;i++)
        Wt[(size_t)(n0+ty+i*8)*K+k0+tx]=__float2half_rn(t[tx][ty+i*8]);
}

__global__ __launch_bounds__(256)
void cvth(const float* __restrict__ x, __half* __restrict__ o){
    size_t i=(size_t)blockIdx.x*256+threadIdx.x;
    o[i]=__float2half_rn(x[i]);
}

// ---------- LayerNorm (templated output: fp16 or fp32) ----------
template<bool F32OUT>
__global__ __launch_bounds__(256)
void ln_kernel(const float* __restrict__ x, const float* __restrict__ w,
               const float* __restrict__ b, __half* __restrict__ oh, float* __restrict__ of)
{
    int row=blockIdx.x;
    const float* xr=x+(size_t)row*Cc;
    float v[4], s=0.f, ss=0.f;
#pragma unroll
    for(int i=0;i<4;i++){ v[i]=xr[threadIdx.x+i*256]; s+=v[i]; ss+=v[i]*v[i]; }
#pragma unroll
    for(int off=16;off;off>>=1){ s+=__shfl_xor_sync(~0u,s,off); ss+=__shfl_xor_sync(~0u,ss,off); }
    __shared__ float red[16]; __shared__ float mean_s, rstd_s;
    int w8=threadIdx.x>>5;
    if((threadIdx.x&31)==0){ red[w8]=s; red[8+w8]=ss; }
    __syncthreads();
    if(threadIdx.x==0){
        float S=0.f,SS=0.f;
#pragma unroll
        for(int i=0;i<8;i++){ S+=red[i]; SS+=red[8+i]; }
        float m=S*(1.0f/Cc);
        mean_s=m; rstd_s=rsqrtf(SS*(1.0f/Cc)-m*m+LN_EPS);
    }
    __syncthreads();
    float m=mean_s, r=rstd_s;
    size_t rb=(size_t)row*Cc;
#pragma unroll
    for(int i=0;i<4;i++){
        int c=threadIdx.x+i*256;
        float y=(v[i]-m)*r*w[c]+b[c];
        if(F32OUT) of[rb+c]=y; else oh[rb+c]=__float2half_rn(y);
    }
}

// ---------- bucketed local attention -> ctx fp16 ----------
constexpr int ATTN_SMEM=(64*65+128*65+128*65+64*129)*4;

__global__ __launch_bounds__(256)
void attn_kernel(const float* __restrict__ qkv, __half* __restrict__ ch)
{
    extern __shared__ float sm[];
    float* q=sm; float* kc=q+64*65; float* vc=kc+128*65; float* s=vc+128*65;
    const int n=blockIdx.x, h=blockIdx.y, bb=blockIdx.z;
    const int tid=threadIdx.x;
    const size_t rowbase=(size_t)(bb*Tt+n*BSz);
    const float* base=qkv+rowbase*(3*Cc);
    const int hoff=h*HD;

    for(int e=tid;e<64*64;e+=256){ int i=e>>6,d=e&63; q[i*65+d]=base[(size_t)i*3072+hoff+d]; }
    for(int e=tid;e<128*64;e+=256){
        int j=e>>6,d=e&63; float kv,vv;
        if(j<64){
            if(n==0){ kv=0.f; vv=0.f; }
            else{ const float* pb=qkv+(rowbase-64+j)*3072; kv=pb[1024+hoff+d]; vv=pb[2048+hoff+d]; }
        } else {
            const float* cb=base+(size_t)(j-64)*3072; kv=cb[1024+hoff+d]; vv=cb[2048+hoff+d];
        }
        kc[j*65+d]=kv; vc[j*65+d]=vv;
    }
    __syncthreads();
    {
        int i=tid>>2, jq=tid&3;
        float acc[32];
#pragma unroll
        for(int jj=0;jj<32;jj++) acc[jj]=0.f;
#pragma unroll 4
        for(int d=0;d<64;d++){
            float qv=q[i*65+d];
#pragma unroll
            for(int jj=0;jj<32;jj++) acc[jj]+=qv*kc[(jq+jj*4)*65+d];
        }
#pragma unroll
        for(int jj=0;jj<32;jj++){
            int j=jq+jj*4;
            bool vis=(j<64)||((j-64)<=i);
            s[i*129+j]=vis?acc[jj]*ATT_SCALE:-1e30f;
        }
    }
    __syncthreads();
    if(tid<64){
        float mx=-1e30f;
        for(int j=0;j<128;j++) mx=fmaxf(mx,s[tid*129+j]);
        float sum=0.f;
        for(int j=0;j<128;j++){ float e=expf(s[tid*129+j]-mx); s[tid*129+j]=e; sum+=e; }
        float inv=1.0f/sum;
        for(int j=0;j<128;j++) s[tid*129+j]*=inv;
    }
    __syncthreads();
    {
        int i=tid>>2, dq=tid&3;
        float acc[16];
#pragma unroll
        for(int dd=0;dd<16;dd++) acc[dd]=0.f;
        for(int j=0;j<128;j++){
            float av=s[i*129+j];
#pragma unroll
            for(int dd=0;dd<16;dd++) acc[dd]+=av*vc[j*65+dq+dd*4];
        }
        size_t ob=(rowbase+i)*Cc+hoff;
#pragma unroll
        for(int dd=0;dd<16;dd++) ch[ob+dq+dd*4]=__float2half_rn(acc[dd]);
    }
}

// ---------- actor head: fp32 SIMT, block = 8 rows ----------
__global__ __launch_bounds__(256)
void actor_head(const float* __restrict__ hb, const float* __restrict__ aw,
                const float* __restrict__ ab, float* __restrict__ out)
{
    __shared__ float rows[8][1024];
    int r0=blockIdx.x*8;
    for(int e=threadIdx.x;e<8*1024;e+=256)
        rows[e>>10][e&1023]=hb[(size_t)(r0+(e>>10))*Cc+(e&1023)];
    __syncthreads();
    int a=threadIdx.x&63, rs=threadIdx.x>>6;
#pragma unroll
    for(int rr=0;rr<2;rr++){
        int r=rs*2+rr;
        float sum=0.f;
        for(int k=0;k<1024;k++) sum+=rows[r][k]*aw[k*64+a];
        out[(size_t)(r0+r)*64+a]=sum+ab[a];
    }
}

// ---------- critic head + logstd (fp32) ----------
__global__ __launch_bounds__(256)
void head_small(const float* __restrict__ hb, const float* __restrict__ cw,
                const float* __restrict__ cb, const float* __restrict__ lstd,
                float* __restrict__ out)
{
    int row=blockIdx.x*8+(threadIdx.x>>5);
    int lane=threadIdx.x&31;
    const float* hr=hb+(size_t)row*Cc;
    float sum=0.f;
#pragma unroll 8
    for(int k=lane;k<Cc;k+=32) sum+=hr[k]*cw[k];
#pragma unroll
    for(int off=16;off;off>>=1) sum+=__shfl_xor_sync(~0u,sum,off);
    if(lane==0) out[(size_t)Mm*Aa+Aa+row]=sum+cb[0];
    if(blockIdx.x==0 && threadIdx.x<Aa) out[(size_t)Mm*Aa+threadIdx.x]=lstd[threadIdx.x];
}

// ---------- launcher ----------
extern "C" void kernel_launch(void* const* d_in, const int* in_sizes, int n_in,
                              void* d_out, int out_size)
{
    const float* states=(const float*)d_in[0];
    const float* se_w=(const float*)d_in[1];  const float* se_b=(const float*)d_in[2];
    const float* pos =(const float*)d_in[3];
    const float* ln1w=(const float*)d_in[4];  const float* ln1b=(const float*)d_in[5];
    const float* qkvw=(const float*)d_in[6];  const float* qkvb=(const float*)d_in[7];
    const float* aow =(const float*)d_in[8];  const float* aob =(const float*)d_in[9];
    const float* ln2w=(const float*)d_in[10]; const float* ln2b=(const float*)d_in[11];
    const float* w1  =(const float*)d_in[12]; const float* b1  =(const float*)d_in[13];
    const float* w2  =(const float*)d_in[14]; const float* b2  =(const float*)d_in[15];
    const float* lnfw=(const float*)d_in[16]; const float* lnfb=(const float*)d_in[17];
    const float* actw=(const float*)d_in[18]; const float* actb=(const float*)d_in[19];
    const float* lstd=(const float*)d_in[20];
    const float* crw =(const float*)d_in[21]; const float* crb =(const float*)d_in[22];
    float* out=(float*)d_out;

    float *x,*qkv;
    __half *sh,*hh,*ch,*mh,*wh;
    cudaGetSymbolAddress((void**)&x,g_x);    cudaGetSymbolAddress((void**)&qkv,g_qkv);
    cudaGetSymbolAddress((void**)&sh,g_sh);  cudaGetSymbolAddress((void**)&hh,g_hh);
    cudaGetSymbolAddress((void**)&ch,g_ch);  cudaGetSymbolAddress((void**)&mh,g_mh);
    cudaGetSymbolAddress((void**)&wh,g_wh);

    cudaFuncSetAttribute(gemmh<0>, cudaFuncAttributeMaxDynamicSharedMemorySize, GSMEM);
    cudaFuncSetAttribute(gemmh<1>, cudaFuncAttributeMaxDynamicSharedMemorySize, GSMEM);
    cudaFuncSetAttribute(gemmh<2>, cudaFuncAttributeMaxDynamicSharedMemorySize, GSMEM);
    cudaFuncSetAttribute(gemmh<3>, cudaFuncAttributeMaxDynamicSharedMemorySize, GSMEM);
    cudaFuncSetAttribute(attn_kernel, cudaFuncAttributeMaxDynamicSharedMemorySize, ATTN_SMEM);

    const dim3 gC(4,Mm/128), g3C(12,Mm/128), g4C(16,Mm/128);

    trk<<<dim3(1024/32,256/32),256>>>(se_w, wh+SE_OFF, 256,1024);
    cvth<<<Mm*SD/256,256>>>(states, sh);
    gemmh<3><<<gC,GTHREADS,GSMEM>>>(sh, wh+SE_OFF, se_b, pos, x, nullptr, 1024,256);

    for(int l=0;l<Ll;l++){
        ln_kernel<false><<<Mm,256>>>(x, ln1w+l*Cc, ln1b+l*Cc, hh, nullptr);
        trk<<<dim3(3072/32,1024/32),256>>>(qkvw+(size_t)l*QKV_SZ, wh+QKV_OFF+l*QKV_SZ, 1024,3072);
        gemmh<0><<<g3C,GTHREADS,GSMEM>>>(hh, wh+QKV_OFF+l*QKV_SZ, qkvb+(size_t)l*3072, nullptr, qkv, nullptr, 3072,1024);
        attn_kernel<<<dim3(Tt/BSz,Hh,Bb),256,ATTN_SMEM>>>(qkv, ch);
        trk<<<dim3(1024/32,1024/32),256>>>(aow+(size_t)l*AO_SZ, wh+AO_OFF+l*AO_SZ, 1024,1024);
        gemmh<2><<<gC,GTHREADS,GSMEM>>>(ch, wh+AO_OFF+l*AO_SZ, aob+(size_t)l*1024, x, x, nullptr, 1024,1024);
        ln_kernel<false><<<Mm,256>>>(x, ln2w+l*Cc, ln2b+l*Cc, hh, nullptr);
        trk<<<dim3(4096/32,1024/32),256>>>(w1+(size_t)l*W1_SZ, wh+W1_OFF+l*W1_SZ, 1024,4096);
        gemmh<1><<<g4C,GTHREADS,GSMEM>>>(hh, wh+W1_OFF+l*W1_SZ, b1+(size_t)l*4096, nullptr, nullptr, mh, 4096,1024);
        trk<<<dim3(1024/32,4096/32),256>>>(w2+(size_t)l*W2_SZ, wh+W2_OFF+l*W2_SZ, 4096,1024);
        gemmh<2><<<gC,GTHREADS,GSMEM>>>(mh, wh+W2_OFF+l*W2_SZ, b2+(size_t)l*1024, x, x, nullptr, 1024,4096);
    }

    // final LN -> fp32 (reuse qkv buffer), heads in fp32 SIMT
    ln_kernel<true><<<Mm,256>>>(x, lnfw, lnfb, nullptr, qkv);
    actor_head<<<Mm/8,256>>>(qkv, actw, actb, out);
    head_small<<<Mm/8,256>>>(qkv, crw, crb, lstd, out);
}

// round 17
// speedup vs baseline: 1.2025x; 1.2025x over previous
#include <cuda_runtime.h>
#include <cuda_fp16.h>
#include <cstdint>
#include <cmath>

constexpr int Bb=4, Tt=4096, SD=256, Cc=1024, Aa=64, Ll=6, Hh=16, BSz=64;
constexpr int Mm=Bb*Tt, HD=Cc/Hh;
constexpr float ATT_SCALE=0.125f, LN_EPS=1e-5f;

// transposed fp16 weights, packed (element offsets)
constexpr size_t SE_OFF=0;
constexpr size_t QKV_OFF=SE_OFF+1024UL*256, QKV_SZ=3072UL*1024;
constexpr size_t AO_OFF =QKV_OFF+6*QKV_SZ,  AO_SZ =1024UL*1024;
constexpr size_t W1_OFF =AO_OFF +6*AO_SZ,   W1_SZ =4096UL*1024;
constexpr size_t W2_OFF =W1_OFF +6*W1_SZ,   W2_SZ =1024UL*4096;
constexpr size_t WTOT   =W2_OFF +6*W2_SZ;

__device__ float g_x  [(size_t)Mm*Cc];       // residual stream (fp32)
__device__ float g_qkv[(size_t)Mm*3*Cc];     // qkv fp32 / final-LN fp32 reuse
__device__ __half g_sh[(size_t)Mm*SD];       // states fp16
__device__ __half g_hh[(size_t)Mm*Cc];       // LN out fp16
__device__ __half g_ch[(size_t)Mm*Cc];       // attn ctx fp16
__device__ __half g_mh[(size_t)Mm*4*Cc];     // mlp hidden fp16
__device__ __half g_wh[WTOT];                // weights fp16 [N][K]

// ---------- base-target PTX helpers ----------
__device__ __forceinline__ uint32_t smem_u32(const void* p){
    uint32_t a; asm("{ .reg .u64 t; cvta.to.shared.u64 t, %1; cvt.u32.u64 %0, t; }":"=r"(a):"l"(p)); return a;
}
__device__ __forceinline__ void cpa16(uint32_t dst, const void* src){
    asm volatile("cp.async.cg.shared.global [%0], [%1], 16;"::"r"(dst),"l"(src));
}
#define CP_COMMIT() asm volatile("cp.async.commit_group;":::"memory")
__device__ __forceinline__ void ldsm4(uint32_t* r, uint32_t a){
    asm volatile("ldmatrix.sync.aligned.m8n8.x4.shared.b16 {%0,%1,%2,%3}, [%4];"
        : "=r"(r[0]),"=r"(r[1]),"=r"(r[2]),"=r"(r[3]) : "r"(a));
}
__device__ __forceinline__ void mma16816(float* d, const uint32_t* a, const uint32_t* b){
    asm volatile("mma.sync.aligned.m16n8k16.row.col.f32.f16.f16.f32 "
        "{%0,%1,%2,%3}, {%4,%5,%6,%7}, {%8,%9}, {%0,%1,%2,%3};"
        : "+f"(d[0]),"+f"(d[1]),"+f"(d[2]),"+f"(d[3])
        : "r"(a[0]),"r"(a[1]),"r"(a[2]),"r"(a[3]), "r"(b[0]),"r"(b[1]));
}
__device__ __forceinline__ float gelu_exact(float x){
    return 0.5f*x*(1.0f+erff(x*0.70710678118654752f));
}

// ========== fp16 GEMM: out = EPI(A[M,K] @ Bt[N,K]^T + bias) ==========
// CTA tile 128(M) x NBT(N), 8 warps (2M x 4N), K-step 32, 3-stage cp.async.
// NBT=256 for wide-N GEMMs (best MMA:ldsm ratio), NBT=128 for N=1024 (wave quantization).
// smem row: 32 fp16 (64B) at 80B stride. CP_COMMIT unconditional (wait_group accounting).
// EPI: 0 = fp32 out; 1 = gelu -> fp16; 2 = +aux residual fp32; 3 = +pos-embed fp32
constexpr int BOFF=10240;
constexpr int GSMEM256=3*(10240+256*80);   // 92160
constexpr int GSMEM128=3*(10240+128*80);   // 61440

template<int EPI,int NBT>
__global__ __launch_bounds__(256)
void gemmh(const __half* __restrict__ Ah, const __half* __restrict__ Bt,
           const float* __restrict__ bias, const float* __restrict__ aux,
           float* __restrict__ outF, __half* __restrict__ oH, int Nv, int K)
{
    constexpr int WN_W=NBT/4, NG=NBT/64, NT=NBT/32;
    constexpr int STAGE=10240+NBT*80;
    extern __shared__ char smem[];
    const uint32_t sb = smem_u32(smem);
    const int tid=threadIdx.x, lane=tid&31, wid=tid>>5;
    const int wm=wid>>2, wn=wid&3;                 // 2 x 4 warps
    const int m0=blockIdx.y*128, n0=blockIdx.x*NBT;
    const int nk=K>>5;

    auto issue=[&](int buf,int k0){
        uint32_t ab=sb+buf*STAGE;
#pragma unroll
        for(int i=0;i<2;i++){                       // A: 128 rows x 4 chunks
            int c=tid+i*256;
            int r=c>>2, qd=c&3;
            cpa16(ab+r*80+qd*16, Ah+(size_t)(m0+r)*K+k0+qd*8);
        }
#pragma unroll
        for(int i=0;i<NBT/64;i++){                  // B: NBT rows x 4 chunks
            int c=tid+i*256;
            int r=c>>2, qd=c&3;
            cpa16(ab+BOFF+r*80+qd*16, Bt+(size_t)(n0+r)*K+k0+qd*8);
        }
    };

    float acc[4][NT][4];
#pragma unroll
    for(int a=0;a<4;a++)
#pragma unroll
    for(int b=0;b<NT;b++)
#pragma unroll
    for(int c=0;c<4;c++) acc[a][b][c]=0.f;

    issue(0,0); CP_COMMIT();
    issue(1,32); CP_COMMIT();

    int buf=0;
    for(int s=0;s<nk;s++){
        asm volatile("cp.async.wait_group 1;":::"memory");
        __syncthreads();
        uint32_t ab=sb+buf*STAGE, bbs=ab+BOFF;
#pragma unroll
        for(int p=0;p<2;p++){
            uint32_t bfr[NG][4];
#pragma unroll
            for(int ng=0;ng<NG;ng++){
                uint32_t nrow=wn*WN_W+ng*16+((lane>>4)&1)*8+(lane&7);
                uint32_t kby =((lane>>3)&1)*16+p*32;
                ldsm4(bfr[ng], bbs+nrow*80+kby);
            }
            uint32_t afr[4][4];
#pragma unroll
            for(int mt=0;mt<4;mt++){
                uint32_t row=wm*64+mt*16+((lane>>3)&1)*8+(lane&7);
                uint32_t kby=((lane>>4)&1)*16+p*32;
                ldsm4(afr[mt], ab+row*80+kby);
            }
#pragma unroll
            for(int mt=0;mt<4;mt++)
#pragma unroll
            for(int nt=0;nt<NT;nt++)
                mma16816(acc[mt][nt], afr[mt], &bfr[nt>>1][(nt&1)*2]);
        }
        if(s+2<nk) issue((buf+2)%3,(s+2)*32);
        CP_COMMIT();                                 // unconditional
        buf=(buf+1)%3;
    }

    // ---- epilogue ----
#pragma unroll
    for(int mt=0;mt<4;mt++)
#pragma unroll
    for(int nt=0;nt<NT;nt++){
        int col=n0+wn*WN_W+nt*8+2*(lane&3);
        int r0=m0+wm*64+mt*16+(lane>>2);
        float2 bv=*(const float2*)(bias+col);
#pragma unroll
        for(int hrow=0;hrow<2;hrow++){
            int r=r0+hrow*8;
            float v0=acc[mt][nt][hrow*2+0]+bv.x;
            float v1=acc[mt][nt][hrow*2+1]+bv.y;
            size_t o=(size_t)r*Nv+col;
            if(EPI==1){
                v0=gelu_exact(v0); v1=gelu_exact(v1);
                __half2 hp; hp.x=__float2half_rn(v0); hp.y=__float2half_rn(v1);
                *(__half2*)(oH+o)=hp;
            } else if(EPI==2){
                float2 ax=*(const float2*)(aux+o);
                *(float2*)(outF+o)=make_float2(v0+ax.x, v1+ax.y);
            } else if(EPI==3){
                float2 ax=*(const float2*)(aux+(size_t)(r&(Tt-1))*Nv+col);
                *(float2*)(outF+o)=make_float2(v0+ax.x, v1+ax.y);
            } else {
                *(float2*)(outF+o)=make_float2(v0,v1);
            }
        }
    }
}

// ---------- weight transpose + fp16: W[K,N] -> Wt[N,K] ----------
__global__ __launch_bounds__(256)
void trk(const float* __restrict__ W, __half* __restrict__ Wt, int K, int N)
{
    __shared__ float t[32][33];
    int n0=blockIdx.x*32, k0=blockIdx.y*32;
    int tx=threadIdx.x&31, ty=threadIdx.x>>5;
#pragma unroll
    for(int i=0;i<4;i++) t[ty+i*8][tx]=W[(size_t)(k0+ty+i*8)*N+n0+tx];
    __syncthreads();
#pragma unroll
    for(int i=0;i<4;i++)
        Wt[(size_t)(n0+ty+i*8)*K+k0+tx]=__float2half_rn(t[tx][ty+i*8]);
}

__global__ __launch_bounds__(256)
void cvth(const float* __restrict__ x, __half* __restrict__ o){
    size_t i=(size_t)blockIdx.x*256+threadIdx.x;
    o[i]=__float2half_rn(x[i]);
}

// ---------- LayerNorm (templated output: fp16 or fp32) ----------
template<bool F32OUT>
__global__ __launch_bounds__(256)
void ln_kernel(const float* __restrict__ x, const float* __restrict__ w,
               const float* __restrict__ b, __half* __restrict__ oh, float* __restrict__ of)
{
    int row=blockIdx.x;
    const float* xr=x+(size_t)row*Cc;
    float v[4], s=0.f, ss=0.f;
#pragma unroll
    for(int i=0;i<4;i++){ v[i]=xr[threadIdx.x+i*256]; s+=v[i]; ss+=v[i]*v[i]; }
#pragma unroll
    for(int off=16;off;off>>=1){ s+=__shfl_xor_sync(~0u,s,off); ss+=__shfl_xor_sync(~0u,ss,off); }
    __shared__ float red[16]; __shared__ float mean_s, rstd_s;
    int w8=threadIdx.x>>5;
    if((threadIdx.x&31)==0){ red[w8]=s; red[8+w8]=ss; }
    __syncthreads();
    if(threadIdx.x==0){
        float S=0.f,SS=0.f;
#pragma unroll
        for(int i=0;i<8;i++){ S+=red[i]; SS+=red[8+i]; }
        float m=S*(1.0f/Cc);
        mean_s=m; rstd_s=rsqrtf(SS*(1.0f/Cc)-m*m+LN_EPS);
    }
    __syncthreads();
    float m=mean_s, r=rstd_s;
    size_t rb=(size_t)row*Cc;
#pragma unroll
    for(int i=0;i<4;i++){
        int c=threadIdx.x+i*256;
        float y=(v[i]-m)*r*w[c]+b[c];
        if(F32OUT) of[rb+c]=y; else oh[rb+c]=__float2half_rn(y);
    }
}

// ---------- bucketed local attention (register-blocked fp32) -> ctx fp16 ----------
// smem: q[64][68], kc[128][68] (d-swizzled), vc[128][68], s[64][132]
constexpr int QS=68, SS=132;
constexpr int ATTN_SMEM=(64*QS+128*QS+128*QS+64*SS)*4;   // 120832 B

__global__ __launch_bounds__(256)
void attn_kernel(const float* __restrict__ qkv, __half* __restrict__ ch)
{
    extern __shared__ float sm[];
    float* q=sm; float* kc=q+64*QS; float* vc=kc+128*QS; float* s=vc+128*QS;
    const int n=blockIdx.x, h=blockIdx.y, bb=blockIdx.z;
    const int tid=threadIdx.x;
    const size_t rowbase=(size_t)(bb*Tt+n*BSz);
    const float* base=qkv+rowbase*3072;
    const int hoff=h*HD;

    for(int e=tid;e<64*64;e+=256){ int i=e>>6,d=e&63; q[i*QS+d]=base[(size_t)i*3072+hoff+d]; }
    for(int e=tid;e<128*64;e+=256){
        int j=e>>6,d=e&63; float kv,vv;
        if(j<64){
            if(n==0){ kv=0.f; vv=0.f; }
            else{ const float* pb=qkv+(rowbase-64+j)*3072; kv=pb[1024+hoff+d]; vv=pb[2048+hoff+d]; }
        } else {
            const float* cb=base+(size_t)(j-64)*3072; kv=cb[1024+hoff+d]; vv=cb[2048+hoff+d];
        }
        kc[j*QS+(d^((j>>3)<<2))]=kv;     // swizzle: conflict-free 8-key column reads
        vc[j*QS+d]=vv;
    }
    __syncthreads();

    // scores: thread (ti,tj) computes queries i0..i0+3 x keys j0..j0+7
    {
        int ti=tid>>4, tj=tid&15;
        int i0=ti*4, j0=tj*8, swz=tj<<2;
        float acc[4][8];
#pragma unroll
        for(int a=0;a<4;a++)
#pragma unroll
        for(int b=0;b<8;b++) acc[a][b]=0.f;
#pragma unroll 4
        for(int d=0;d<64;d++){
            float qv[4], kv[8];
#pragma unroll
            for(int ii=0;ii<4;ii++) qv[ii]=q[(i0+ii)*QS+d];
            int dk=d^swz;
#pragma unroll
            for(int jj=0;jj<8;jj++) kv[jj]=kc[(j0+jj)*QS+dk];
#pragma unroll
            for(int ii=0;ii<4;ii++)
#pragma unroll
            for(int jj=0;jj<8;jj++) acc[ii][jj]+=qv[ii]*kv[jj];
        }
#pragma unroll
        for(int ii=0;ii<4;ii++)
#pragma unroll
        for(int jj=0;jj<8;jj++){
            int j=j0+jj, i=i0+ii;
            bool vis=(j<64)||((j-64)<=i);
            s[i*SS+j]=vis?acc[ii][jj]*ATT_SCALE:-1e30f;
        }
    }
    __syncthreads();

    // softmax: 4 threads per query row
    {
        int row=tid>>2, p=tid&3;
        float ev[32], mx=-1e30f;
#pragma unroll
        for(int jj=0;jj<32;jj++){ ev[jj]=s[row*SS+p*32+jj]; mx=fmaxf(mx,ev[jj]); }
        mx=fmaxf(mx,__shfl_xor_sync(~0u,mx,1));
        mx=fmaxf(mx,__shfl_xor_sync(~0u,mx,2));
        float sum=0.f;
#pragma unroll
        for(int jj=0;jj<32;jj++){ ev[jj]=expf(ev[jj]-mx); sum+=ev[jj]; }
        sum+=__shfl_xor_sync(~0u,sum,1);
        sum+=__shfl_xor_sync(~0u,sum,2);
        float inv=1.0f/sum;
#pragma unroll
        for(int jj=0;jj<32;jj++) s[row*SS+p*32+jj]=ev[jj]*inv;
    }
    __syncthreads();

    // AV: thread (ig,dg) computes queries i0..i0+3 x dims d0..d0+3, causal early-exit
    {
        int ig=tid>>4, dg=tid&15;
        int i0=ig*4, d0=dg*4;
        float a4[4][4];
#pragma unroll
        for(int a=0;a<4;a++)
#pragma unroll
        for(int b=0;b<4;b++) a4[a][b]=0.f;
        int jmax=min(128, i0+68);          // beyond: softmax weights are exactly 0
        for(int j=0;j<jmax;j++){
            float4 vv=*(const float4*)&vc[j*QS+d0];
#pragma unroll
            for(int ii=0;ii<4;ii++){
                float av=s[(i0+ii)*SS+j];
                a4[ii][0]+=av*vv.x; a4[ii][1]+=av*vv.y;
                a4[ii][2]+=av*vv.z; a4[ii][3]+=av*vv.w;
            }
        }
#pragma unroll
        for(int ii=0;ii<4;ii++){
            __half2 h0=__floats2half2_rn(a4[ii][0],a4[ii][1]);
            __half2 h1=__floats2half2_rn(a4[ii][2],a4[ii][3]);
            size_t ob=(rowbase+i0+ii)*Cc+hoff+d0;
            *(__half2*)(ch+ob)=h0;
            *(__half2*)(ch+ob+2)=h1;
        }
    }
}

// ---------- actor head: fp32 SIMT, block = 8 rows ----------
__global__ __launch_bounds__(256)
void actor_head(const float* __restrict__ hb, const float* __restrict__ aw,
                const float* __restrict__ ab, float* __restrict__ out)
{
    __shared__ float rows[8][1024];
    int r0=blockIdx.x*8;
    for(int e=threadIdx.x;e<8*1024;e+=256)
        rows[e>>10][e&1023]=hb[(size_t)(r0+(e>>10))*Cc+(e&1023)];
    __syncthreads();
    int a=threadIdx.x&63, rs=threadIdx.x>>6;
#pragma unroll
    for(int rr=0;rr<2;rr++){
        int r=rs*2+rr;
        float sum=0.f;
        for(int k=0;k<1024;k++) sum+=rows[r][k]*aw[k*64+a];
        out[(size_t)(r0+r)*64+a]=sum+ab[a];
    }
}

// ---------- critic head + logstd (fp32) ----------
__global__ __launch_bounds__(256)
void head_small(const float* __restrict__ hb, const float* __restrict__ cw,
                const float* __restrict__ cb, const float* __restrict__ lstd,
                float* __restrict__ out)
{
    int row=blockIdx.x*8+(threadIdx.x>>5);
    int lane=threadIdx.x&31;
    const float* hr=hb+(size_t)row*Cc;
    float sum=0.f;
#pragma unroll 8
    for(int k=lane;k<Cc;k+=32) sum+=hr[k]*cw[k];
#pragma unroll
    for(int off=16;off;off>>=1) sum+=__shfl_xor_sync(~0u,sum,off);
    if(lane==0) out[(size_t)Mm*Aa+Aa+row]=sum+cb[0];
    if(blockIdx.x==0 && threadIdx.x<Aa) out[(size_t)Mm*Aa+threadIdx.x]=lstd[threadIdx.x];
}

// ---------- launcher ----------
extern "C" void kernel_launch(void* const* d_in, const int* in_sizes, int n_in,
                              void* d_out, int out_size)
{
    const float* states=(const float*)d_in[0];
    const float* se_w=(const float*)d_in[1];  const float* se_b=(const float*)d_in[2];
    const float* pos =(const float*)d_in[3];
    const float* ln1w=(const float*)d_in[4];  const float* ln1b=(const float*)d_in[5];
    const float* qkvw=(const float*)d_in[6];  const float* qkvb=(const float*)d_in[7];
    const float* aow =(const float*)d_in[8];  const float* aob =(const float*)d_in[9];
    const float* ln2w=(const float*)d_in[10]; const float* ln2b=(const float*)d_in[11];
    const float* w1  =(const float*)d_in[12]; const float* b1  =(const float*)d_in[13];
    const float* w2  =(const float*)d_in[14]; const float* b2  =(const float*)d_in[15];
    const float* lnfw=(const float*)d_in[16]; const float* lnfb=(const float*)d_in[17];
    const float* actw=(const float*)d_in[18]; const float* actb=(const float*)d_in[19];
    const float* lstd=(const float*)d_in[20];
    const float* crw =(const float*)d_in[21]; const float* crb =(const float*)d_in[22];
    float* out=(float*)d_out;

    float *x,*qkv;
    __half *sh,*hh,*ch,*mh,*wh;
    cudaGetSymbolAddress((void**)&x,g_x);    cudaGetSymbolAddress((void**)&qkv,g_qkv);
    cudaGetSymbolAddress((void**)&sh,g_sh);  cudaGetSymbolAddress((void**)&hh,g_hh);
    cudaGetSymbolAddress((void**)&ch,g_ch);  cudaGetSymbolAddress((void**)&mh,g_mh);
    cudaGetSymbolAddress((void**)&wh,g_wh);

    cudaFuncSetAttribute(gemmh<0,256>, cudaFuncAttributeMaxDynamicSharedMemorySize, GSMEM256);
    cudaFuncSetAttribute(gemmh<1,256>, cudaFuncAttributeMaxDynamicSharedMemorySize, GSMEM256);
    cudaFuncSetAttribute(gemmh<2,128>, cudaFuncAttributeMaxDynamicSharedMemorySize, GSMEM128);
    cudaFuncSetAttribute(gemmh<3,128>, cudaFuncAttributeMaxDynamicSharedMemorySize, GSMEM128);
    cudaFuncSetAttribute(attn_kernel, cudaFuncAttributeMaxDynamicSharedMemorySize, ATTN_SMEM);

    const dim3 gC128(8,Mm/128), g3C(12,Mm/128), g4C(16,Mm/128);

    trk<<<dim3(1024/32,256/32),256>>>(se_w, wh+SE_OFF, 256,1024);
    cvth<<<Mm*SD/256,256>>>(states, sh);
    gemmh<3,128><<<gC128,256,GSMEM128>>>(sh, wh+SE_OFF, se_b, pos, x, nullptr, 1024,256);

    for(int l=0;l<Ll;l++){
        ln_kernel<false><<<Mm,256>>>(x, ln1w+l*Cc, ln1b+l*Cc, hh, nullptr);
        trk<<<dim3(3072/32,1024/32),256>>>(qkvw+(size_t)l*QKV_SZ, wh+QKV_OFF+l*QKV_SZ, 1024,3072);
        gemmh<0,256><<<g3C,256,GSMEM256>>>(hh, wh+QKV_OFF+l*QKV_SZ, qkvb+(size_t)l*3072, nullptr, qkv, nullptr, 3072,1024);
        attn_kernel<<<dim3(Tt/BSz,Hh,Bb),256,ATTN_SMEM>>>(qkv, ch);
        trk<<<dim3(1024/32,1024/32),256>>>(aow+(size_t)l*AO_SZ, wh+AO_OFF+l*AO_SZ, 1024,1024);
        gemmh<2,128><<<gC128,256,GSMEM128>>>(ch, wh+AO_OFF+l*AO_SZ, aob+(size_t)l*1024, x, x, nullptr, 1024,1024);
        ln_kernel<false><<<Mm,256>>>(x, ln2w+l*Cc, ln2b+l*Cc, hh, nullptr);
        trk<<<dim3(4096/32,1024/32),256>>>(w1+(size_t)l*W1_SZ, wh+W1_OFF+l*W1_SZ, 1024,4096);
        gemmh<1,256><<<g4C,256,GSMEM256>>>(hh, wh+W1_OFF+l*W1_SZ, b1+(size_t)l*4096, nullptr, nullptr, mh, 4096,1024);
        trk<<<dim3(1024/32,4096/32),256>>>(w2+(size_t)l*W2_SZ, wh+W2_OFF+l*W2_SZ, 4096,1024);
        gemmh<2,128><<<gC128,256,GSMEM128>>>(mh, wh+W2_OFF+l*W2_SZ, b2+(size_t)l*1024, x, x, nullptr, 1024,4096);
    }

    // final LN -> fp32 (reuse qkv buffer), heads in fp32 SIMT
    ln_kernel<true><<<Mm,256>>>(x, lnfw, lnfb, nullptr, qkv);
    actor_head<<<Mm/8,256>>>(qkv, actw, actb, out);
    head_small<<<Mm/8,256>>>(qkv, crw, crb, lstd, out);
}